// round 17
// baseline (speedup 1.0000x reference)
#include <cuda_runtime.h>
#include <cuda_bf16.h>
#include <cstdint>

#define B_  16
#define N_  1024
#define O_  64
#define H_  1024
#define D_  256

#define MV  (B_ * N_)      // 16384
#define MP  (B_ * O_)      // 1024
#define NQ  4              // token quarters
#define QN  (N_ / NQ)      // 256 tokens per quarter

#define LOG_OFF  0
#define ATT_OFF  (B_ * O_)
#define EV_OFF   (ATT_OFF + B_ * O_ * N_)
#define LOSS_OFF (EV_OFF + B_ * O_ * D_)

// ---------------- device scratch ----------------
__device__ float g_phrase[MP * D_];
__device__ float g_accum[2];
__device__ float g_evpart[NQ * MP * D_];
__device__ float g_ms[NQ * MP * 2];

__device__ __align__(16) __nv_bfloat16 g_wv_hi[H_ * D_];
__device__ __align__(16) __nv_bfloat16 g_wv_lo[H_ * D_];
__device__ __align__(16) __nv_bfloat16 g_wp_hi[H_ * D_];
__device__ __align__(16) __nv_bfloat16 g_wp_lo[H_ * D_];

__device__ __align__(16) __nv_bfloat16 g_vis_hi[MV * D_];
__device__ __align__(16) __nv_bfloat16 g_vis_lo[MV * D_];
__device__ __align__(16) __nv_bfloat16 g_proto_hi[MP * D_];
__device__ __align__(16) __nv_bfloat16 g_proto_lo[MP * D_];

// ---------------- helpers ----------------
__device__ __forceinline__ uint32_t smem_u32(const void* p) {
    uint32_t a;
    asm("{ .reg .u64 t; cvta.to.shared.u64 t, %1; cvt.u32.u64 %0, t; }" : "=r"(a) : "l"(p));
    return a;
}
__device__ __forceinline__ void cpa16(uint32_t s, const void* g) {
    asm volatile("cp.async.cg.shared.global [%0], [%1], 16;" :: "r"(s), "l"(g));
}
#define CP_COMMIT() asm volatile("cp.async.commit_group;" ::: "memory")
#define CP_WAIT1()  asm volatile("cp.async.wait_group 1;" ::: "memory")
#define CP_WAIT0()  asm volatile("cp.async.wait_group 0;" ::: "memory")

__device__ __forceinline__ void ldm_x4(uint32_t* r, uint32_t a) {
    asm volatile("ldmatrix.sync.aligned.m8n8.x4.shared.b16 {%0,%1,%2,%3}, [%4];"
        : "=r"(r[0]), "=r"(r[1]), "=r"(r[2]), "=r"(r[3]) : "r"(a));
}
__device__ __forceinline__ void ldm_x2(uint32_t* r, uint32_t a) {
    asm volatile("ldmatrix.sync.aligned.m8n8.x2.shared.b16 {%0,%1}, [%2];"
        : "=r"(r[0]), "=r"(r[1]) : "r"(a));
}
__device__ __forceinline__ void ldm_x4t(uint32_t* r, uint32_t a) {
    asm volatile("ldmatrix.sync.aligned.m8n8.x4.trans.shared.b16 {%0,%1,%2,%3}, [%4];"
        : "=r"(r[0]), "=r"(r[1]), "=r"(r[2]), "=r"(r[3]) : "r"(a));
}
__device__ __forceinline__ void mma16816(float* c, const uint32_t* a, const uint32_t* b) {
    asm volatile(
        "mma.sync.aligned.m16n8k16.row.col.f32.bf16.bf16.f32 "
        "{%0,%1,%2,%3}, {%4,%5,%6,%7}, {%8,%9}, {%0,%1,%2,%3};"
        : "+f"(c[0]), "+f"(c[1]), "+f"(c[2]), "+f"(c[3])
        : "r"(a[0]), "r"(a[1]), "r"(a[2]), "r"(a[3]), "r"(b[0]), "r"(b[1]));
}

__device__ __forceinline__ float warp_sum(float v) {
    #pragma unroll
    for (int o = 16; o > 0; o >>= 1) v += __shfl_xor_sync(0xffffffffu, v, o);
    return v;
}

__device__ __forceinline__ void split_pair(float x, float y, __nv_bfloat16* hi, __nv_bfloat16* lo) {
    __nv_bfloat162 h, l;
    h.x = __float2bfloat16(x); h.y = __float2bfloat16(y);
    l.x = __float2bfloat16(x - __bfloat162float(h.x));
    l.y = __float2bfloat16(y - __bfloat162float(h.y));
    *(__nv_bfloat162*)hi = h;
    *(__nv_bfloat162*)lo = l;
}

__device__ __forceinline__ uint32_t bf2pack(float a, float b) {
    __nv_bfloat162 h;
    h.x = __float2bfloat16(a); h.y = __float2bfloat16(b);
    return *(uint32_t*)&h;
}

__device__ __forceinline__ void split8(const float4& A, const float4& B, uint4& hi, uint4& lo) {
    hi.x = bf2pack(A.x, A.y); hi.y = bf2pack(A.z, A.w);
    hi.z = bf2pack(B.x, B.y); hi.w = bf2pack(B.z, B.w);
    __nv_bfloat162 h;
    *(uint32_t*)&h = hi.x; lo.x = bf2pack(A.x - __bfloat162float(h.x), A.y - __bfloat162float(h.y));
    *(uint32_t*)&h = hi.y; lo.y = bf2pack(A.z - __bfloat162float(h.x), A.w - __bfloat162float(h.y));
    *(uint32_t*)&h = hi.z; lo.z = bf2pack(B.x - __bfloat162float(h.x), B.y - __bfloat162float(h.y));
    *(uint32_t*)&h = hi.w; lo.w = bf2pack(B.z - __bfloat162float(h.x), B.w - __bfloat162float(h.y));
}

__device__ __forceinline__ void split_one(const float* __restrict__ x,
                                          __nv_bfloat16* __restrict__ hi,
                                          __nv_bfloat16* __restrict__ lo, int i)
{
    float4 v = ((const float4*)x)[i];
    uint4 h, l;
    split8(v, v, h, l);
    ((uint32_t*)hi)[i * 2]     = h.x;
    ((uint32_t*)hi)[i * 2 + 1] = h.y;
    ((uint32_t*)lo)[i * 2]     = l.x;
    ((uint32_t*)lo)[i * 2 + 1] = l.y;
}

__global__ __launch_bounds__(256) void k_split_w(const float* __restrict__ Wv,
                                                 const float* __restrict__ Wp)
{
    if (blockIdx.x == 0 && threadIdx.x == 0) { g_accum[0] = 0.0f; g_accum[1] = 0.0f; }
    const int n4 = H_ * D_ / 4;
    for (int i = blockIdx.x * blockDim.x + threadIdx.x; i < 2 * n4; i += gridDim.x * blockDim.x) {
        if (i < n4) split_one(Wv, g_wv_hi, g_wv_lo, i);
        else        split_one(Wp, g_wp_hi, g_wp_lo, i - n4);
    }
}

// ---------------- mma.sync GEMM, BM=64 BN=256 BK=32 ----------------
// Single sync per stage: A double-buffered (STS), B triple-buffered (cp.async, 2-deep).
#define NSTAGE (H_ / 32)
#define ABUF_SZ 8192           // 4KB hi + 4KB lo
#define BBUF_SZ 32768          // 16KB hi + 16KB lo
#define ST_B0 (2 * ABUF_SZ)    // 16384
#define GEMM_SMEM (ST_B0 + 3 * BBUF_SZ)   // 114688

__global__ __launch_bounds__(256, 2) void k_gemm_mma(const float* __restrict__ visA,
                                                     const float* __restrict__ phrA,
                                                     const float* __restrict__ bv,
                                                     const float* __restrict__ bp,
                                                     const float* __restrict__ proto)
{
    extern __shared__ char smem[];
    const uint32_t sb = smem_u32(smem);
    const int tid = threadIdx.x;
    const int lane = tid & 31;
    const int wid = tid >> 5;
    const int wm = wid & 1;
    const int wn = wid >> 1;

    const bool isV = blockIdx.x < (MV / 64);
    const float* Afp;
    const __nv_bfloat16 *Bh, *Bl;
    const float* bias;
    int m0;
    if (isV) { Afp = visA; Bh = g_wv_hi; Bl = g_wv_lo; bias = bv; m0 = blockIdx.x * 64; }
    else     { Afp = phrA; Bh = g_wp_hi; Bl = g_wp_lo; bias = bp; m0 = (blockIdx.x - MV / 64) * 64; }

    const int a_r = tid >> 2;
    const int a_c = tid & 3;
    const uint32_t a_so = (uint32_t)(a_r * 64 + ((a_c ^ ((a_r >> 1) & 3)) << 4));
    const float* Arow = Afp + (size_t)(m0 + a_r) * H_ + a_c * 8;

    const int b_r = tid >> 3;
    const int b_c = tid & 7;
    uint32_t b_so[4];
    #pragma unroll
    for (int q = 0; q < 4; q++)
        b_so[q] = (uint32_t)(b_r * 512 + (((b_c + q * 8) ^ (b_r & 7)) << 4));

    float acc[2][8][4];
    #pragma unroll
    for (int i = 0; i < 2; i++)
        #pragma unroll
        for (int j = 0; j < 8; j++)
            #pragma unroll
            for (int k = 0; k < 4; k++) acc[i][j][k] = 0.0f;

    // ---- prologue ----
    // A(0) -> regs -> split -> bufA0 ; fa <- A(1)
    {
        float4 f0 = *(const float4*)(Arow);
        float4 f1 = *(const float4*)(Arow + 4);
        uint4 h, l;
        split8(f0, f1, h, l);
        *(uint4*)(smem + a_so)           = h;
        *(uint4*)(smem + 4096 + a_so)    = l;
    }
    float4 fa0 = *(const float4*)(Arow + 32);
    float4 fa1 = *(const float4*)(Arow + 36);
    // B(0), B(1) in flight
    #pragma unroll
    for (int ss = 0; ss < 2; ss++) {
        const uint32_t bb = sb + ST_B0 + ss * BBUF_SZ;
        const int k0 = ss * 32;
        #pragma unroll
        for (int q = 0; q < 4; q++) {
            cpa16(bb + b_so[q],         Bh + (size_t)(k0 + b_r) * D_ + (b_c + q * 8) * 8);
            cpa16(bb + 16384 + b_so[q], Bl + (size_t)(k0 + b_r) * D_ + (b_c + q * 8) * 8);
        }
        CP_COMMIT();
    }

    for (int s = 0; s < NSTAGE; s++) {
        if (s + 1 < NSTAGE) { CP_WAIT1(); } else { CP_WAIT0(); }
        __syncthreads();   // B(s) + A(s) visible; all warps done with stage s-1 buffers

        // issue B(s+2) into ring slot (s+2)%3  (last read at stage s-1)
        if (s + 2 < NSTAGE) {
            const uint32_t bb = sb + ST_B0 + ((s + 2) % 3) * BBUF_SZ;
            const int k0 = (s + 2) * 32;
            #pragma unroll
            for (int q = 0; q < 4; q++) {
                cpa16(bb + b_so[q],         Bh + (size_t)(k0 + b_r) * D_ + (b_c + q * 8) * 8);
                cpa16(bb + 16384 + b_so[q], Bl + (size_t)(k0 + b_r) * D_ + (b_c + q * 8) * 8);
            }
        }
        CP_COMMIT();

        // store A(s+1) into bufA[(s+1)&1] (last read at stage s-1); prefetch A(s+2)
        if (s + 1 < NSTAGE) {
            uint4 h, l;
            split8(fa0, fa1, h, l);
            const uint32_t ab = (uint32_t)(((s + 1) & 1) * ABUF_SZ);
            *(uint4*)(smem + ab + a_so)        = h;
            *(uint4*)(smem + ab + 4096 + a_so) = l;
        }
        if (s + 2 < NSTAGE) {
            fa0 = *(const float4*)(Arow + (s + 2) * 32);
            fa1 = *(const float4*)(Arow + (s + 2) * 32 + 4);
        }

        const uint32_t aBase = sb + (uint32_t)((s & 1) * ABUF_SZ);
        const uint32_t bBase = sb + ST_B0 + (uint32_t)((s % 3) * BBUF_SZ);

        #pragma unroll
        for (int ks = 0; ks < 2; ks++) {
            uint32_t ahf[2][4], alf[2][4];
            #pragma unroll
            for (int mf = 0; mf < 2; mf++) {
                const int row = wm * 32 + mf * 16 + ((lane >> 3) & 1) * 8 + (lane & 7);
                const int ch  = ks * 2 + (lane >> 4);
                const uint32_t addr = aBase + (uint32_t)(row * 64 + ((ch ^ ((row >> 1) & 3)) << 4));
                ldm_x4(ahf[mf], addr);
                ldm_x4(alf[mf], addr + 4096);
            }
            #pragma unroll
            for (int g = 0; g < 4; g++) {
                const int row = ks * 16 + ((lane >> 3) & 1) * 8 + (lane & 7);
                const int ch  = wn * 8 + g * 2 + (lane >> 4);
                const uint32_t addr = bBase + (uint32_t)(row * 512 + ((ch ^ (row & 7)) << 4));
                uint32_t th[4], tl[4];
                ldm_x4t(th, addr);
                ldm_x4t(tl, addr + 16384);
                uint32_t bh0[2] = {th[0], th[1]}, bh1[2] = {th[2], th[3]};
                uint32_t bl0[2] = {tl[0], tl[1]}, bl1[2] = {tl[2], tl[3]};
                #pragma unroll
                for (int mf = 0; mf < 2; mf++) {
                    mma16816(acc[mf][g * 2],     ahf[mf], bh0);
                    mma16816(acc[mf][g * 2],     ahf[mf], bl0);
                    mma16816(acc[mf][g * 2],     alf[mf], bh0);
                    mma16816(acc[mf][g * 2 + 1], ahf[mf], bh1);
                    mma16816(acc[mf][g * 2 + 1], ahf[mf], bl1);
                    mma16816(acc[mf][g * 2 + 1], alf[mf], bh1);
                }
            }
        }
        // no trailing sync — next stage's single barrier gates buffer reuse
    }
    __syncthreads();

    // ---- epilogue: bias + fused L2 row-normalize ----
    #pragma unroll
    for (int mf = 0; mf < 2; mf++)
        #pragma unroll
        for (int nf = 0; nf < 8; nf++) {
            const int n = wn * 64 + nf * 8 + (lane & 3) * 2;
            const float bx = bias[n], by = bias[n + 1];
            acc[mf][nf][0] += bx; acc[mf][nf][1] += by;
            acc[mf][nf][2] += bx; acc[mf][nf][3] += by;
        }

    float* part = (float*)smem;
    #pragma unroll
    for (int mf = 0; mf < 2; mf++) {
        float p0 = 0.0f, p1 = 0.0f;
        #pragma unroll
        for (int nf = 0; nf < 8; nf++) {
            p0 = fmaf(acc[mf][nf][0], acc[mf][nf][0], p0);
            p0 = fmaf(acc[mf][nf][1], acc[mf][nf][1], p0);
            p1 = fmaf(acc[mf][nf][2], acc[mf][nf][2], p1);
            p1 = fmaf(acc[mf][nf][3], acc[mf][nf][3], p1);
        }
        p0 += __shfl_xor_sync(0xffffffffu, p0, 1);
        p0 += __shfl_xor_sync(0xffffffffu, p0, 2);
        p1 += __shfl_xor_sync(0xffffffffu, p1, 1);
        p1 += __shfl_xor_sync(0xffffffffu, p1, 2);
        if ((lane & 3) == 0) {
            const int r = wm * 32 + mf * 16 + (lane >> 2);
            part[wn * 64 + r]     = p0;
            part[wn * 64 + r + 8] = p1;
        }
    }
    __syncthreads();

    #pragma unroll
    for (int mf = 0; mf < 2; mf++) {
        const int r0 = wm * 32 + mf * 16 + (lane >> 2);
        const int r1 = r0 + 8;
        const float s0 = part[r0] + part[64 + r0] + part[128 + r0] + part[192 + r0];
        const float s1 = part[r1] + part[64 + r1] + part[128 + r1] + part[192 + r1];
        const float inv0 = 1.0f / fmaxf(sqrtf(s0), 1e-12f);
        const float inv1 = 1.0f / fmaxf(sqrtf(s1), 1e-12f);
        #pragma unroll
        for (int nf = 0; nf < 8; nf++) {
            const int n = wn * 64 + nf * 8 + (lane & 3) * 2;
            acc[mf][nf][0] *= inv0; acc[mf][nf][1] *= inv0;
            acc[mf][nf][2] *= inv1; acc[mf][nf][3] *= inv1;
            if (isV) {
                split_pair(acc[mf][nf][0], acc[mf][nf][1],
                           &g_vis_hi[(size_t)(m0 + r0) * D_ + n], &g_vis_lo[(size_t)(m0 + r0) * D_ + n]);
                split_pair(acc[mf][nf][2], acc[mf][nf][3],
                           &g_vis_hi[(size_t)(m0 + r1) * D_ + n], &g_vis_lo[(size_t)(m0 + r1) * D_ + n]);
            } else {
                float2 w0; w0.x = acc[mf][nf][0]; w0.y = acc[mf][nf][1];
                float2 w1; w1.x = acc[mf][nf][2]; w1.y = acc[mf][nf][3];
                *(float2*)&g_phrase[(size_t)(m0 + r0) * D_ + n] = w0;
                *(float2*)&g_phrase[(size_t)(m0 + r1) * D_ + n] = w1;
            }
        }
    }

    if (!isV) {
        __syncthreads();
        #pragma unroll
        for (int mf = 0; mf < 2; mf++) {
            const int r0l = wm * 32 + mf * 16 + (lane >> 2);
            float p0 = 0.0f, p1 = 0.0f;
            #pragma unroll
            for (int nf = 0; nf < 8; nf++) {
                const int n = wn * 64 + nf * 8 + (lane & 3) * 2;
                const float2 pr0 = *(const float2*)&proto[(size_t)r0l * D_ + n];
                const float2 pr1 = *(const float2*)&proto[(size_t)(r0l + 8) * D_ + n];
                acc[mf][nf][0] += pr0.x; acc[mf][nf][1] += pr0.y;
                acc[mf][nf][2] += pr1.x; acc[mf][nf][3] += pr1.y;
                p0 = fmaf(acc[mf][nf][0], acc[mf][nf][0], p0);
                p0 = fmaf(acc[mf][nf][1], acc[mf][nf][1], p0);
                p1 = fmaf(acc[mf][nf][2], acc[mf][nf][2], p1);
                p1 = fmaf(acc[mf][nf][3], acc[mf][nf][3], p1);
            }
            p0 += __shfl_xor_sync(0xffffffffu, p0, 1);
            p0 += __shfl_xor_sync(0xffffffffu, p0, 2);
            p1 += __shfl_xor_sync(0xffffffffu, p1, 1);
            p1 += __shfl_xor_sync(0xffffffffu, p1, 2);
            if ((lane & 3) == 0) {
                const int r = wm * 32 + mf * 16 + (lane >> 2);
                part[wn * 64 + r]     = p0;
                part[wn * 64 + r + 8] = p1;
            }
        }
        __syncthreads();
        #pragma unroll
        for (int mf = 0; mf < 2; mf++) {
            const int r0 = wm * 32 + mf * 16 + (lane >> 2);
            const int r1 = r0 + 8;
            const float s0 = part[r0] + part[64 + r0] + part[128 + r0] + part[192 + r0];
            const float s1 = part[r1] + part[64 + r1] + part[128 + r1] + part[192 + r1];
            const float inv0 = 1.0f / fmaxf(sqrtf(s0), 1e-12f);
            const float inv1 = 1.0f / fmaxf(sqrtf(s1), 1e-12f);
            #pragma unroll
            for (int nf = 0; nf < 8; nf++) {
                const int n = wn * 64 + nf * 8 + (lane & 3) * 2;
                split_pair(acc[mf][nf][0] * inv0, acc[mf][nf][1] * inv0,
                           &g_proto_hi[(size_t)(m0 + r0) * D_ + n], &g_proto_lo[(size_t)(m0 + r0) * D_ + n]);
                split_pair(acc[mf][nf][2] * inv1, acc[mf][nf][3] * inv1,
                           &g_proto_hi[(size_t)(m0 + r1) * D_ + n], &g_proto_lo[(size_t)(m0 + r1) * D_ + n]);
            }
        }
    }
}

// ---------------- split-KV flash attention, 16 o's/CTA, token quarters ------
#define AS_VH 0
#define AS_VL 32768
#define AS_PH 65536
#define AS_PL 73728
#define AS_EH 81920
#define AS_EL 84096
#define AS_RED 86272
#define RED_M    (AS_RED + 0)
#define RED_S    (AS_RED + 64)
#define RED_F    (AS_RED + 128)
#define RED_WMAX (AS_RED + 192)
#define RED_ESUM (AS_RED + 704)
#define ATT_SMEM (AS_RED + 1216)

__global__ __launch_bounds__(256, 2) void k_attn_mma(float* __restrict__ out)
{
    extern __shared__ char smem[];
    const uint32_t sb = smem_u32(smem);
    const int tid = threadIdx.x, lane = tid & 31, w = tid >> 5;
    const int og = blockIdx.x, b = blockIdx.y, qtr = blockIdx.z;
    const int row0 = b * O_ + og * 16;
    const int t0 = qtr * QN;
    const int r0 = lane >> 2;

    #pragma unroll
    for (int i = tid; i < 512; i += 256) {
        const int r = i >> 5, ch = i & 31;
        const uint32_t off = (uint32_t)(r * 512 + ((ch ^ (r & 7)) << 4));
        const size_t src = (size_t)(row0 + r) * D_ + ch * 8;
        cpa16(sb + AS_PH + off, g_proto_hi + src);
        cpa16(sb + AS_PL + off, g_proto_lo + src);
    }
    CP_COMMIT();

    const __nv_bfloat16* vh = g_vis_hi + ((size_t)(b * N_ + t0)) * D_;
    const __nv_bfloat16* vl = g_vis_lo + ((size_t)(b * N_ + t0)) * D_;
    float* mred = (float*)(smem + RED_M);
    float* sred = (float*)(smem + RED_S);
    float* fred = (float*)(smem + RED_F);
    float* wmax = (float*)(smem + RED_WMAX);
    float* esum = (float*)(smem + RED_ESUM);

    if (tid < 16) { mred[tid] = -1e30f; sred[tid] = 0.0f; }

    float eacc[4][4];
    #pragma unroll
    for (int i = 0; i < 4; i++)
        #pragma unroll
        for (int j = 0; j < 4; j++) eacc[i][j] = 0.0f;

    for (int tile = 0; tile < QN / 64; tile++) {
        for (int i = tid; i < 2048; i += 256) {
            const int r = i >> 5, ch = i & 31;
            const uint32_t off = (uint32_t)(r * 512 + ((ch ^ (r & 7)) << 4));
            const size_t src = (size_t)(tile * 64 + r) * D_ + ch * 8;
            cpa16(sb + AS_VH + off, vh + src);
            cpa16(sb + AS_VL + off, vl + src);
        }
        CP_COMMIT();
        CP_WAIT0();
        __syncthreads();

        float sacc[4] = {0.f, 0.f, 0.f, 0.f};
        #pragma unroll
        for (int ks = 0; ks < 16; ks++) {
            const int arow = ((lane >> 3) & 1) * 8 + (lane & 7);
            const int ach = ks * 2 + (lane >> 4);
            const uint32_t aoff = (uint32_t)(arow * 512 + ((ach ^ (arow & 7)) << 4));
            uint32_t ah[4], al[4];
            ldm_x4(ah, sb + AS_PH + aoff);
            ldm_x4(al, sb + AS_PL + aoff);
            const int brow = w * 8 + (lane & 7);
            const int bch = ks * 2 + ((lane >> 3) & 1);
            const uint32_t boff = (uint32_t)(brow * 512 + ((bch ^ (brow & 7)) << 4));
            uint32_t bh[2], bl[2];
            ldm_x2(bh, sb + AS_VH + boff);
            ldm_x2(bl, sb + AS_VL + boff);
            mma16816(sacc, ah, bh);
            mma16816(sacc, ah, bl);
            mma16816(sacc, al, bh);
        }

        float t0m = fmaxf(sacc[0], sacc[1]);
        t0m = fmaxf(t0m, __shfl_xor_sync(0xffffffffu, t0m, 1));
        t0m = fmaxf(t0m, __shfl_xor_sync(0xffffffffu, t0m, 2));
        float t1m = fmaxf(sacc[2], sacc[3]);
        t1m = fmaxf(t1m, __shfl_xor_sync(0xffffffffu, t1m, 1));
        t1m = fmaxf(t1m, __shfl_xor_sync(0xffffffffu, t1m, 2));
        if ((lane & 3) == 0) {
            wmax[r0 * 8 + w]       = t0m;
            wmax[(r0 + 8) * 8 + w] = t1m;
        }
        __syncthreads();
        if (tid < 16) {
            float mx = mred[tid];
            #pragma unroll
            for (int ww = 0; ww < 8; ww++) mx = fmaxf(mx, wmax[tid * 8 + ww]);
            fred[tid] = expf(mred[tid] - mx);
            mred[tid] = mx;
        }
        __syncthreads();

        const float m0r = mred[r0];
        const float m1r = mred[r0 + 8];
        const float e0 = expf(sacc[0] - m0r);
        const float e1 = expf(sacc[1] - m0r);
        const float e2 = expf(sacc[2] - m1r);
        const float e3 = expf(sacc[3] - m1r);
        {
            const int n = t0 + tile * 64 + w * 8 + (lane & 3) * 2;
            float2 s0v; s0v.x = sacc[0]; s0v.y = sacc[1];
            float2 s1v; s1v.x = sacc[2]; s1v.y = sacc[3];
            *(float2*)&out[ATT_OFF + (size_t)(row0 + r0) * N_ + n]     = s0v;
            *(float2*)&out[ATT_OFF + (size_t)(row0 + r0 + 8) * N_ + n] = s1v;
        }
        {
            const uint32_t e0off = (uint32_t)(r0 * 128 + ((w ^ (r0 & 7)) << 4) + (lane & 3) * 4);
            const uint32_t e1off = e0off + 8 * 128;
            split_pair(e0, e1, (__nv_bfloat16*)(smem + AS_EH + e0off), (__nv_bfloat16*)(smem + AS_EL + e0off));
            split_pair(e2, e3, (__nv_bfloat16*)(smem + AS_EH + e1off), (__nv_bfloat16*)(smem + AS_EL + e1off));
        }
        float q0 = e0 + e1;
        q0 += __shfl_xor_sync(0xffffffffu, q0, 1);
        q0 += __shfl_xor_sync(0xffffffffu, q0, 2);
        float q1 = e2 + e3;
        q1 += __shfl_xor_sync(0xffffffffu, q1, 1);
        q1 += __shfl_xor_sync(0xffffffffu, q1, 2);
        if ((lane & 3) == 0) {
            esum[r0 * 8 + w]       = q0;
            esum[(r0 + 8) * 8 + w] = q1;
        }
        const float fr0 = fred[r0];
        const float fr1 = fred[r0 + 8];
        #pragma unroll
        for (int nf = 0; nf < 4; nf++) {
            eacc[nf][0] *= fr0; eacc[nf][1] *= fr0;
            eacc[nf][2] *= fr1; eacc[nf][3] *= fr1;
        }
        __syncthreads();
        if (tid < 16) {
            float ssum = 0.0f;
            #pragma unroll
            for (int ww = 0; ww < 8; ww++) ssum += esum[tid * 8 + ww];
            sred[tid] = sred[tid] * fred[tid] + ssum;
        }

        #pragma unroll
        for (int ksl = 0; ksl < 4; ksl++) {
            const int arow = ((lane >> 3) & 1) * 8 + (lane & 7);
            const int ach = ksl * 2 + (lane >> 4);
            const uint32_t aoff = (uint32_t)(arow * 128 + ((ach ^ (arow & 7)) << 4));
            uint32_t ah[4], al[4];
            ldm_x4(ah, sb + AS_EH + aoff);
            ldm_x4(al, sb + AS_EL + aoff);
            #pragma unroll
            for (int g = 0; g < 2; g++) {
                const int brow = ksl * 16 + ((lane >> 3) & 1) * 8 + (lane & 7);
                const int bch = w * 4 + g * 2 + (lane >> 4);
                const uint32_t boff = (uint32_t)(brow * 512 + ((bch ^ (brow & 7)) << 4));
                uint32_t th[4], tl[4];
                ldm_x4t(th, sb + AS_VH + boff);
                ldm_x4t(tl, sb + AS_VL + boff);
                uint32_t bh0[2] = {th[0], th[1]}, bh1[2] = {th[2], th[3]};
                uint32_t bl0[2] = {tl[0], tl[1]}, bl1[2] = {tl[2], tl[3]};
                mma16816(eacc[g * 2],     ah, bh0);
                mma16816(eacc[g * 2],     ah, bl0);
                mma16816(eacc[g * 2],     al, bh0);
                mma16816(eacc[g * 2 + 1], ah, bh1);
                mma16816(eacc[g * 2 + 1], ah, bl1);
                mma16816(eacc[g * 2 + 1], al, bh1);
            }
        }
        __syncthreads();
    }

    {
        const int grow0 = row0 + r0;
        const int grow1 = grow0 + 8;
        #pragma unroll
        for (int nf = 0; nf < 4; nf++) {
            const int d = w * 32 + nf * 8 + (lane & 3) * 2;
            float2 ev0; ev0.x = eacc[nf][0]; ev0.y = eacc[nf][1];
            float2 ev1; ev1.x = eacc[nf][2]; ev1.y = eacc[nf][3];
            *(float2*)&g_evpart[((size_t)qtr * MP + grow0) * D_ + d] = ev0;
            *(float2*)&g_evpart[((size_t)qtr * MP + grow1) * D_ + d] = ev1;
        }
    }
    if (tid < 16) {
        g_ms[((size_t)qtr * MP + row0 + tid) * 2]     = mred[tid];
        g_ms[((size_t)qtr * MP + row0 + tid) * 2 + 1] = sred[tid];
    }
}

// ---------------- combine quarters ----------------
__global__ __launch_bounds__(256) void k_attn_fin(
    const float* __restrict__ labels, const float* __restrict__ Wc,
    const float* __restrict__ bcp, float* __restrict__ out)
{
    __shared__ float s_log[8];
    __shared__ float s_loss[8];
    __shared__ float s_ent[8];
    const int row = blockIdx.x;
    const int tid = threadIdx.x, lane = tid & 31, w = tid >> 5;

    float m[NQ], s[NQ];
    #pragma unroll
    for (int q = 0; q < NQ; q++) {
        m[q] = g_ms[((size_t)q * MP + row) * 2];
        s[q] = g_ms[((size_t)q * MP + row) * 2 + 1];
    }
    float mstar = m[0];
    #pragma unroll
    for (int q = 1; q < NQ; q++) mstar = fmaxf(mstar, m[q]);
    float f[NQ], sstar = 0.0f;
    #pragma unroll
    for (int q = 0; q < NQ; q++) { f[q] = expf(m[q] - mstar); sstar += s[q] * f[q]; }
    const float inv = 1.0f / sstar;

    float* att = out + ATT_OFF + (size_t)row * N_;
    float ent = 0.0f;
    {
        float4 v = *(float4*)&att[tid * 4];
        float4 p;
        p.x = expf(v.x - mstar) * inv;
        p.y = expf(v.y - mstar) * inv;
        p.z = expf(v.z - mstar) * inv;
        p.w = expf(v.w - mstar) * inv;
        *(float4*)&att[tid * 4] = p;
        ent += p.x * logf(fmaxf(p.x, 1e-8f));
        ent += p.y * logf(fmaxf(p.y, 1e-8f));
        ent += p.z * logf(fmaxf(p.z, 1e-8f));
        ent += p.w * logf(fmaxf(p.w, 1e-8f));
    }

    const int d = tid;
    float ev = 0.0f;
    #pragma unroll
    for (int q = 0; q < NQ; q++)
        ev += g_evpart[((size_t)q * MP + row) * D_ + d] * f[q];
    ev *= inv;
    out[EV_OFF + (size_t)row * D_ + d] = ev;
    float lp = ev * Wc[d];
    const float lab = labels[row];
    const float df = ev - lab * g_phrase[(size_t)row * D_ + d];
    float lsum = df * df;

    ent = warp_sum(ent);
    lp = warp_sum(lp);
    lsum = warp_sum(lsum);
    if (lane == 0) { s_log[w] = lp; s_loss[w] = lsum; s_ent[w] = ent; }
    __syncthreads();
    if (tid == 0) {
        float L = 0.0f, S = 0.0f, E = 0.0f;
        #pragma unroll
        for (int i = 0; i < 8; i++) { L += s_log[i]; S += s_loss[i]; E += s_ent[i]; }
        out[LOG_OFF + row] = L + bcp[0];
        atomicAdd(&g_accum[0], S);
        atomicAdd(&g_accum[1], E);
    }
}

__global__ void k_finalize(float* __restrict__ out) {
    const float proto_loss = g_accum[0] / (float)(B_ * O_ * D_);
    const float sparse_loss = -g_accum[1] / (float)(B_ * O_);
    out[LOSS_OFF] = proto_loss + 0.01f * sparse_loss;
}

// ---------------- launch ----------------
extern "C" void kernel_launch(void* const* d_in, const int* in_sizes, int n_in,
                              void* d_out, int out_size)
{
    (void)in_sizes; (void)n_in; (void)out_size;
    const float* visual_tokens = (const float*)d_in[0];
    const float* phrase_states = (const float*)d_in[1];
    const float* labels        = (const float*)d_in[2];
    const float* Wv            = (const float*)d_in[3];
    const float* bv            = (const float*)d_in[4];
    const float* Wp            = (const float*)d_in[5];
    const float* bp            = (const float*)d_in[6];
    const float* proto         = (const float*)d_in[7];
    const float* Wc            = (const float*)d_in[8];
    const float* bc            = (const float*)d_in[9];
    float* out = (float*)d_out;

    cudaFuncSetAttribute(k_gemm_mma, cudaFuncAttributeMaxDynamicSharedMemorySize, GEMM_SMEM);
    cudaFuncSetAttribute(k_attn_mma, cudaFuncAttributeMaxDynamicSharedMemorySize, ATT_SMEM);

    k_split_w<<<512, 256>>>(Wv, Wp);
    k_gemm_mma<<<MV / 64 + MP / 64, 256, GEMM_SMEM>>>(visual_tokens, phrase_states, bv, bp, proto);
    k_attn_mma<<<dim3(4, B_, NQ), 256, ATT_SMEM>>>(out);
    k_attn_fin<<<MP, 256>>>(labels, Wc, bc, out);
    k_finalize<<<1, 1>>>(out);
}